// round 16
// baseline (speedup 1.0000x reference)
#include <cuda_runtime.h>
#include <cuda_fp16.h>
#include <cstdint>

#define NB 131072
#define NA 65536
#define NM 2048
#define DH 300
#define AF 133
#define K1 147
#define GF 128
#define OUTC 428

#define KP1 160
#define KP2 320
#define KP3 448

#define SROW 304            // padded intermediate row stride (halves)
#define SR8  19             // 32B chunks per row (608 B)

struct U8 { uint4 a, b; };

// ---------------- device scratch ----------------
__device__ __align__(32) __half g_W1[320 * KP1];
__device__ __align__(32) __half g_W2[320 * KP2];
__device__ __align__(32) __half g_W3[320 * KP3];
__device__ __align__(32) __half g_inph [(size_t)NB * SROW];
__device__ __align__(32) __half g_m1h  [(size_t)NB * SROW];
__device__ __align__(32) __half g_m2h  [(size_t)NB * KP2];   // cols 304..319 stay 0
__device__ __align__(32) __half g_h2h  [(size_t)NB * SROW];
__device__ __align__(32) __half g_msgsh[(size_t)NA * SROW];

// ---------------- helpers ----------------
__device__ __forceinline__ uint32_t s2u(const void* p) {
    uint32_t a;
    asm("{ .reg .u64 t; cvta.to.shared.u64 t, %1; cvt.u32.u64 %0, t; }"
        : "=r"(a) : "l"(p));
    return a;
}
__device__ __forceinline__ void cpa16(uint32_t s, const void* g) {
    asm volatile("cp.async.cg.shared.global [%0], [%1], 16;" :: "r"(s), "l"(g));
}
#define CP_COMMIT() asm volatile("cp.async.commit_group;" ::: "memory")
#define CP_WAIT0()  asm volatile("cp.async.wait_group 0;" ::: "memory")

__device__ __forceinline__ void ldmx4(uint32_t* r, uint32_t a) {
    asm volatile("ldmatrix.sync.aligned.m8n8.x4.shared.b16 {%0,%1,%2,%3}, [%4];"
                 : "=r"(r[0]), "=r"(r[1]), "=r"(r[2]), "=r"(r[3]) : "r"(a));
}
__device__ __forceinline__ void ldmx2(uint32_t* r, uint32_t a) {
    asm volatile("ldmatrix.sync.aligned.m8n8.x2.shared.b16 {%0,%1}, [%2];"
                 : "=r"(r[0]), "=r"(r[1]) : "r"(a));
}
__device__ __forceinline__ void mma_f16(float* c, const uint32_t* a, const uint32_t* b) {
    asm volatile(
        "mma.sync.aligned.m16n8k16.row.col.f32.f16.f16.f32 "
        "{%0,%1,%2,%3}, {%4,%5,%6,%7}, {%8,%9}, {%0,%1,%2,%3};"
        : "+f"(c[0]), "+f"(c[1]), "+f"(c[2]), "+f"(c[3])
        : "r"(a[0]), "r"(a[1]), "r"(a[2]), "r"(a[3]), "r"(b[0]), "r"(b[1]));
}
__device__ __forceinline__ __half2 u2h(uint32_t u) { return *(__half2*)&u; }
__device__ __forceinline__ uint32_t h2u(__half2 h) { return *(uint32_t*)&h; }

// 32-byte L2 residency-hinted IO
__device__ __forceinline__ U8 ldg32_el(const __half* p) {
    U8 v;
    asm volatile("ld.global.nc.L2::evict_last.v8.b32 {%0,%1,%2,%3,%4,%5,%6,%7}, [%8];"
                 : "=r"(v.a.x), "=r"(v.a.y), "=r"(v.a.z), "=r"(v.a.w),
                   "=r"(v.b.x), "=r"(v.b.y), "=r"(v.b.z), "=r"(v.b.w) : "l"(p));
    return v;
}
__device__ __forceinline__ void stg32_ef(__half* p, U8 v) {
    asm volatile("st.global.L2::evict_first.v8.b32 [%0], {%1,%2,%3,%4,%5,%6,%7,%8};"
                 :: "l"(p), "r"(v.a.x), "r"(v.a.y), "r"(v.a.z), "r"(v.a.w),
                    "r"(v.b.x), "r"(v.b.y), "r"(v.b.z), "r"(v.b.w) : "memory");
}
__device__ __forceinline__ void stg32_el(__half* p, U8 v) {
    asm volatile("st.global.L2::evict_last.v8.b32 [%0], {%1,%2,%3,%4,%5,%6,%7,%8};"
                 :: "l"(p), "r"(v.a.x), "r"(v.a.y), "r"(v.a.z), "r"(v.a.w),
                    "r"(v.b.x), "r"(v.b.y), "r"(v.b.z), "r"(v.b.w) : "memory");
}

__device__ __forceinline__ uint32_t rsum4(uint32_t a, uint32_t b, uint32_t c, uint32_t d) {
    const __half2 z = __float2half2_rn(0.f);
    __half2 r = __hadd2(__hadd2(__hmax2(u2h(a), z), __hmax2(u2h(b), z)),
                        __hadd2(__hmax2(u2h(c), z), __hmax2(u2h(d), z)));
    return h2u(r);
}
__device__ __forceinline__ uint32_t sum4(uint32_t a, uint32_t b, uint32_t c, uint32_t d) {
    __half2 r = __hadd2(__hadd2(u2h(a), u2h(b)), __hadd2(u2h(c), u2h(d)));
    return h2u(r);
}
__device__ __forceinline__ uint4 rsum16(uint4 a, uint4 b, uint4 c, uint4 d) {
    uint4 o;
    o.x = rsum4(a.x, b.x, c.x, d.x);
    o.y = rsum4(a.y, b.y, c.y, d.y);
    o.z = rsum4(a.z, b.z, c.z, d.z);
    o.w = rsum4(a.w, b.w, c.w, d.w);
    return o;
}
__device__ __forceinline__ uint4 sum16(uint4 a, uint4 b, uint4 c, uint4 d) {
    uint4 o;
    o.x = sum4(a.x, b.x, c.x, d.x);
    o.y = sum4(a.y, b.y, c.y, d.y);
    o.z = sum4(a.z, b.z, c.z, d.z);
    o.w = sum4(a.w, b.w, c.w, d.w);
    return o;
}
__device__ __forceinline__ U8 rsum32(U8 a, U8 b, U8 c, U8 d) {
    U8 o;
    o.a = rsum16(a.a, b.a, c.a, d.a);
    o.b = rsum16(a.b, b.b, c.b, d.b);
    return o;
}
__device__ __forceinline__ U8 sum32(U8 a, U8 b, U8 c, U8 d) {
    U8 o;
    o.a = sum16(a.a, b.a, c.a, d.a);
    o.b = sum16(a.b, b.b, c.b, d.b);
    return o;
}

// ---------------- weight prep (one launch for all 3) ----------------
__global__ void prep_all(const float* __restrict__ W1s,
                         const float* __restrict__ W2s,
                         const float* __restrict__ W3s) {
    int idx = blockIdx.x * 256 + threadIdx.x;
    const int T1 = 320 * KP1, T2 = 320 * KP2;
    const float* W;
    __half* B;
    int KP, mode;
    if (idx < T1) { W = W1s; B = g_W1; KP = KP1; mode = 1; }
    else if (idx < T1 + T2) { idx -= T1; W = W2s; B = g_W2; KP = KP2; mode = 2; }
    else {
        idx -= T1 + T2;
        if (idx >= 320 * KP3) return;
        W = W3s; B = g_W3; KP = KP3; mode = 3;
    }
    int n = idx / KP, k = idx % KP;
    int src;
    if (mode == 3) src = (k < 133) ? k : (k >= 136 && k < 436) ? k - 3 : -1;
    else if (mode == 1) src = (k < K1) ? k : -1;
    else src = (k < DH) ? k : -1;
    float v = (n < 300 && src >= 0) ? W[src * 300 + n] : 0.f;
    B[(size_t)n * KP + k] = __float2half_rn(v);
}

// ---------------- gather1: m1h = sum_j relu(inph[map[j]]) ----------------
__global__ void gather_relu(const int* __restrict__ map) {
    int idx = blockIdx.x * 256 + threadIdx.x;
    if (idx >= NB * SR8) return;
    int r = idx / SR8, c = idx % SR8;
    int4 m = ((const int4*)map)[r];
    const int co = c * 16;
    U8 a = ldg32_el(g_inph + (size_t)m.x * SROW + co);
    U8 b = ldg32_el(g_inph + (size_t)m.y * SROW + co);
    U8 cc = ldg32_el(g_inph + (size_t)m.z * SROW + co);
    U8 d = ldg32_el(g_inph + (size_t)m.w * SROW + co);
    stg32_el(g_m1h + (size_t)r * SROW + co, rsum32(a, b, cc, d));   // m1h re-read 4x
}

// ---------------- gather2: m2h = sum_j m1h[map[j]] -> [NB x 320] ----------------
__global__ void gather2(const int* __restrict__ map) {
    int idx = blockIdx.x * 256 + threadIdx.x;
    if (idx >= NB * SR8) return;
    int r = idx / SR8, c = idx % SR8;
    int4 m = ((const int4*)map)[r];
    const int co = c * 16;
    U8 a = ldg32_el(g_m1h + (size_t)m.x * SROW + co);
    U8 b = ldg32_el(g_m1h + (size_t)m.y * SROW + co);
    U8 cc = ldg32_el(g_m1h + (size_t)m.z * SROW + co);
    U8 d = ldg32_el(g_m1h + (size_t)m.w * SROW + co);
    stg32_ef(g_m2h + (size_t)r * KP2 + co, sum32(a, b, cc, d));
}

// ---------------- gather_atom: msgs = sum_j h2h[a2ib[j]] ----------------
__global__ void gather_atom(const int* __restrict__ a2ib) {
    int idx = blockIdx.x * 256 + threadIdx.x;
    if (idx >= NA * SR8) return;
    int r = idx / SR8, c = idx % SR8;
    int4 m = ((const int4*)a2ib)[r];
    const int co = c * 16;
    U8 a = ldg32_el(g_h2h + (size_t)m.x * SROW + co);
    U8 b = ldg32_el(g_h2h + (size_t)m.y * SROW + co);
    U8 cc = ldg32_el(g_h2h + (size_t)m.z * SROW + co);
    U8 d = ldg32_el(g_h2h + (size_t)m.w * SROW + co);
    stg32_ef(g_msgsh + (size_t)r * SROW + co, sum32(a, b, cc, d));
}

// ---------------- FP16 GEMM: BM=128, BN=320, templated BK, 512 thr, 2 stages ----
// Warp grid 2(m) x 8(n); warp tile 64x40. RS = 2*BK+16 bytes (odd*16 -> conflict-free).
// 2-stage 1-deep pipeline: WAIT0; sync; issue(c+1); compute(c).
template <int MODE, int KP, int BK>
__global__ void __launch_bounds__(512)
mm_f16(const float* __restrict__ srcA,
       const float* __restrict__ bias, float* __restrict__ dOut) {
    constexpr int NCH = KP / BK;
    constexpr int RS = 2 * BK + 16;
    constexpr int BOFF = 128 * RS;
    constexpr int STG = BOFF + 320 * RS;
    constexpr int P2 = (BK + 63) / 64;       // half2-column parts (32 h2-cols each)
    constexpr int NKH = BK / 16;
    constexpr int ASEG = BK / 8;             // 16B segs per row
    const __half* __restrict__ Wt = (MODE == 1) ? g_W1 : (MODE == 2) ? g_W2 : g_W3;

    extern __shared__ __align__(16) char smem[];
    const uint32_t sb = s2u(smem);
    const int tid = threadIdx.x, w = tid >> 5, lane = tid & 31;
    const int wr = w & 1, wc = w >> 1;
    const int rowBase = blockIdx.x * 128;

    float acc[4][5][4];
#pragma unroll
    for (int i = 0; i < 4; i++)
#pragma unroll
        for (int j = 0; j < 5; j++)
#pragma unroll
            for (int q = 0; q < 4; q++) acc[i][j][q] = 0.f;

    // ---- A producer (MODE 1/3): warp owns 8 rows, lane owns half2 column pairs ----
    uint32_t rbuf[8 * P2];
    auto elemA = [&](int grow, int k) -> __half {
        __half v = __float2half_rn(0.f);
        if (MODE == 1) {
            if (k < K1) v = __float2half_rn(srcA[(size_t)grow * K1 + k]);
        } else {
            if (k < AF) v = __float2half_rn(srcA[(size_t)grow * AF + k]);
            else if (k >= 136 && k < 436) v = g_msgsh[(size_t)grow * SROW + (k - 136)];
        }
        return v;
    };
    auto loadA_regs = [&](int c) {
#pragma unroll
        for (int p = 0; p < P2; p++) {
            const int c2 = p * 32 + lane;           // half2 column in chunk
            const bool ok = (2 * c2 < BK);
            const int k0 = c * BK + 2 * c2;
#pragma unroll
            for (int i = 0; i < 8; i++) {
                const int grow = rowBase + w * 8 + i;
                __half2 v = __float2half2_rn(0.f);
                if (ok) {
                    v.x = elemA(grow, k0);
                    v.y = elemA(grow, k0 + 1);
                }
                rbuf[p * 8 + i] = h2u(v);
            }
        }
    };
    auto stsA = [&](int st) {
#pragma unroll
        for (int p = 0; p < P2; p++) {
            const int c2 = p * 32 + lane;
            if (2 * c2 < BK) {
                char* q = smem + st * STG + (w * 8) * RS + c2 * 4;
#pragma unroll
                for (int i = 0; i < 8; i++) *(uint32_t*)(q + i * RS) = rbuf[p * 8 + i];
            }
        }
    };

    // ---- A via cp.async (MODE 2) ----
    auto cpA = [&](int c, int st) {
#pragma unroll
        for (int i = tid; i < 128 * ASEG; i += 512) {
            const int row = i / ASEG, seg = i % ASEG;
            cpa16(sb + st * STG + row * RS + seg * 16,
                  g_m2h + (size_t)(rowBase + row) * KP2 + c * BK + seg * 8);
        }
    };
    auto loadB = [&](int c, int st) {
#pragma unroll
        for (int i = tid; i < 320 * ASEG; i += 512) {
            const int row = i / ASEG, seg = i % ASEG;
            cpa16(sb + st * STG + BOFF + row * RS + seg * 16,
                  Wt + (size_t)row * KP + c * BK + seg * 8);
        }
    };

    // ---- prologue: stage 0 in flight ----
    if (MODE != 2) {
        loadA_regs(0); stsA(0); loadB(0, 0); CP_COMMIT();
        if (NCH > 1) loadA_regs(1);
    } else {
        cpA(0, 0); loadB(0, 0); CP_COMMIT();
    }

    const uint32_t aOff = (uint32_t)(wr * 64 + (lane & 15)) * RS
                        + (uint32_t)(lane >> 4) * 16;
    const int bl = lane & 15;
    const uint32_t bOff = BOFF + (uint32_t)(wc * 40 + (bl & 7)) * RS
                        + (uint32_t)(bl >> 3) * 16;

    for (int c = 0; c < NCH; c++) {
        CP_WAIT0();              // chunk c's group complete
        __syncthreads();         // stage (c-1)&1 free for rewrite
        if (c + 1 < NCH) {
            const int st = (c + 1) & 1;
            if (MODE != 2) { stsA(st); }
            else          { cpA(c + 1, st); }
            loadB(c + 1, st);
            CP_COMMIT();
            if (MODE != 2 && c + 2 < NCH) loadA_regs(c + 2);
        }

        const uint32_t stp = sb + (c & 1) * STG;
#pragma unroll
        for (int kh = 0; kh < NKH; kh++) {
            uint32_t af[4][4], bf[5][2];
#pragma unroll
            for (int mt = 0; mt < 4; mt++)
                ldmx4(af[mt], stp + aOff + mt * (16 * RS) + kh * 32);
#pragma unroll
            for (int nt = 0; nt < 5; nt++)
                ldmx2(bf[nt], stp + bOff + nt * (8 * RS) + kh * 32);
#pragma unroll
            for (int mt = 0; mt < 4; mt++)
#pragma unroll
                for (int nt = 0; nt < 5; nt++)
                    mma_f16(acc[mt][nt], af[mt], bf[nt]);
        }
    }

    if (MODE == 3) {
        // fused per-molecule mean readout: 128 rows = 4 molecules
        const int molBase = blockIdx.x * 4 + wr * 2;
#pragma unroll
        for (int mtb = 0; mtb < 4; mtb += 2) {
#pragma unroll
            for (int nt = 0; nt < 5; nt++) {
                const int col2 = wc * 40 + nt * 8 + (lane & 3) * 2;
                float b0 = 0.f, b1 = 0.f;
                if (col2 < DH) { b0 = bias[col2]; b1 = bias[col2 + 1]; }
                float s0 = 0.f, s1 = 0.f;
#pragma unroll
                for (int p = 0; p < 2; p++) {
#pragma unroll
                    for (int h = 0; h < 2; h++) {
                        s0 += fmaxf(acc[mtb + p][nt][h * 2]     + b0, 0.f);
                        s1 += fmaxf(acc[mtb + p][nt][h * 2 + 1] + b1, 0.f);
                    }
                }
#pragma unroll
                for (int off = 16; off >= 4; off >>= 1) {
                    s0 += __shfl_down_sync(0xFFFFFFFFu, s0, off);
                    s1 += __shfl_down_sync(0xFFFFFFFFu, s1, off);
                }
                if (lane < 4) {
                    const int colw = wc * 40 + nt * 8 + lane * 2;
                    if (colw < DH) {
                        const int mol = molBase + (mtb >> 1);
                        float2 v;
                        v.x = s0 * 0.03125f;
                        v.y = s1 * 0.03125f;
                        *(float2*)&dOut[(size_t)mol * OUTC + colw] = v;
                    }
                }
            }
        }
    } else {
        __half* __restrict__ OUTp = (MODE == 1) ? g_inph : g_h2h;
        const int crow = lane >> 2, cc0 = (lane & 3) * 2;
#pragma unroll
        for (int mt = 0; mt < 4; mt++) {
#pragma unroll
            for (int nt = 0; nt < 5; nt++) {
                const int col = wc * 40 + nt * 8 + cc0;
                if (col >= DH) continue;
#pragma unroll
                for (int half = 0; half < 2; half++) {
                    const int grow = rowBase + wr * 64 + mt * 16 + crow + half * 8;
                    const size_t o = (size_t)grow * SROW + col;
                    float v0 = acc[mt][nt][half * 2];
                    float v1 = acc[mt][nt][half * 2 + 1];
                    if (MODE == 2) {
                        float2 pv = __half22float2(*(const __half2*)&g_inph[o]);
                        v0 = fmaxf(pv.x + v0, 0.f);
                        v1 = fmaxf(pv.y + v1, 0.f);
                    }
                    *(__half2*)&OUTp[o] = __floats2half2_rn(v0, v1);
                }
            }
        }
    }
}

// ---------------- global-feature concat ----------------
__global__ void glob_copy(const float* __restrict__ g, float* __restrict__ out) {
    int idx = blockIdx.x * 256 + threadIdx.x;
    if (idx >= NM * 32) return;
    int mol = idx >> 5, j4 = idx & 31;
    float4 v = ((const float4*)g)[mol * 32 + j4];
    *(float4*)&out[(size_t)mol * OUTC + 300 + 4 * j4] = v;
}

// ---------------- launch ----------------
extern "C" void kernel_launch(void* const* d_in, const int* in_sizes, int n_in,
                              void* d_out, int out_size) {
    const float* atom_features   = (const float*)d_in[0];
    const float* f_ini           = (const float*)d_in[1];
    const float* global_features = (const float*)d_in[2];
    const float* W_i             = (const float*)d_in[3];
    const float* W_h             = (const float*)d_in[4];
    const float* W_o             = (const float*)d_in[5];
    const float* b_o             = (const float*)d_in[6];
    const int*   a2ib            = (const int*)d_in[7];
    const int*   mapping         = (const int*)d_in[8];
    float* out = (float*)d_out;

    const int SM80  = 2 * 448 * 176;   // 157696 (BK=80)
    const int SM112 = 2 * 448 * 240;   // 215040 (BK=112)
    static bool cfg = false;
    if (!cfg) {
        cudaFuncSetAttribute(mm_f16<1, KP1, 80>,  cudaFuncAttributeMaxDynamicSharedMemorySize, SM80);
        cudaFuncSetAttribute(mm_f16<2, KP2, 80>,  cudaFuncAttributeMaxDynamicSharedMemorySize, SM80);
        cudaFuncSetAttribute(mm_f16<3, KP3, 112>, cudaFuncAttributeMaxDynamicSharedMemorySize, SM112);
        cfg = true;
    }

    glob_copy<<<(NM * 32 + 255) / 256, 256>>>(global_features, out);
    prep_all<<<(320 * (KP1 + KP2 + KP3) + 255) / 256, 256>>>(W_i, W_h, W_o);

    // 1) inp = f_ini @ W_i  (BK=80: 2 chunks)
    mm_f16<1, KP1, 80><<<NB / 128, 512, SM80>>>(f_ini, nullptr, nullptr);
    // 2) m1 = sum relu(inp[mapping])
    gather_relu<<<(NB * SR8 + 255) / 256, 256>>>(mapping);
    // 3) m2 = sum m1[mapping]
    gather2<<<(NB * SR8 + 255) / 256, 256>>>(mapping);
    // 4) h2 = relu(inp + m2 @ W_h)  (BK=80: 4 chunks)
    mm_f16<2, KP2, 80><<<NB / 128, 512, SM80>>>(nullptr, nullptr, nullptr);
    // 5) msgs = sum h2[a2ib]
    gather_atom<<<(NA * SR8 + 255) / 256, 256>>>(a2ib);
    // 6+7) out = mean(relu([atomF | msgs] @ W_o + b_o))  (BK=112: 4 chunks)
    mm_f16<3, KP3, 112><<<NA / 128, 512, SM112>>>(atom_features, b_o, out);
}

// round 17
// speedup vs baseline: 1.0840x; 1.0840x over previous
#include <cuda_runtime.h>
#include <cuda_fp16.h>
#include <cstdint>

#define NB 131072
#define NA 65536
#define NM 2048
#define DH 300
#define AF 133
#define K1 147
#define GF 128
#define OUTC 428

#define KP1 160
#define KP2 320
#define KP3 448

#define SROW 304            // padded intermediate row stride (halves)
#define SR8  19             // 32B chunks per row (608 B)
#define GT   10             // gather threads per row (thread t: chunks t, t+10)

struct U8 { uint4 a, b; };

// ---------------- device scratch ----------------
__device__ __align__(32) __half g_W1[320 * KP1];
__device__ __align__(32) __half g_W2[320 * KP2];
__device__ __align__(32) __half g_W3[320 * KP3];
__device__ __align__(32) __half g_inph [(size_t)NB * SROW];
__device__ __align__(32) __half g_m1h  [(size_t)NB * SROW];
__device__ __align__(32) __half g_m2h  [(size_t)NB * KP2];   // cols 304..319 stay 0
__device__ __align__(32) __half g_h2h  [(size_t)NB * SROW];
__device__ __align__(32) __half g_msgsh[(size_t)NA * SROW];

// ---------------- helpers ----------------
__device__ __forceinline__ uint32_t s2u(const void* p) {
    uint32_t a;
    asm("{ .reg .u64 t; cvta.to.shared.u64 t, %1; cvt.u32.u64 %0, t; }"
        : "=r"(a) : "l"(p));
    return a;
}
__device__ __forceinline__ void cpa16(uint32_t s, const void* g) {
    asm volatile("cp.async.cg.shared.global [%0], [%1], 16;" :: "r"(s), "l"(g));
}
#define CP_COMMIT() asm volatile("cp.async.commit_group;" ::: "memory")
#define CP_WAIT1()  asm volatile("cp.async.wait_group 1;" ::: "memory")

__device__ __forceinline__ void ldmx4(uint32_t* r, uint32_t a) {
    asm volatile("ldmatrix.sync.aligned.m8n8.x4.shared.b16 {%0,%1,%2,%3}, [%4];"
                 : "=r"(r[0]), "=r"(r[1]), "=r"(r[2]), "=r"(r[3]) : "r"(a));
}
__device__ __forceinline__ void ldmx2(uint32_t* r, uint32_t a) {
    asm volatile("ldmatrix.sync.aligned.m8n8.x2.shared.b16 {%0,%1}, [%2];"
                 : "=r"(r[0]), "=r"(r[1]) : "r"(a));
}
__device__ __forceinline__ void mma_f16(float* c, const uint32_t* a, const uint32_t* b) {
    asm volatile(
        "mma.sync.aligned.m16n8k16.row.col.f32.f16.f16.f32 "
        "{%0,%1,%2,%3}, {%4,%5,%6,%7}, {%8,%9}, {%0,%1,%2,%3};"
        : "+f"(c[0]), "+f"(c[1]), "+f"(c[2]), "+f"(c[3])
        : "r"(a[0]), "r"(a[1]), "r"(a[2]), "r"(a[3]), "r"(b[0]), "r"(b[1]));
}
__device__ __forceinline__ __half2 u2h(uint32_t u) { return *(__half2*)&u; }
__device__ __forceinline__ uint32_t h2u(__half2 h) { return *(uint32_t*)&h; }

// 32-byte L2 residency-hinted IO (v8.b32 required for hints on this target)
__device__ __forceinline__ U8 ldg32_el(const __half* p) {
    U8 v;
    asm volatile("ld.global.nc.L2::evict_last.v8.b32 {%0,%1,%2,%3,%4,%5,%6,%7}, [%8];"
                 : "=r"(v.a.x), "=r"(v.a.y), "=r"(v.a.z), "=r"(v.a.w),
                   "=r"(v.b.x), "=r"(v.b.y), "=r"(v.b.z), "=r"(v.b.w) : "l"(p));
    return v;
}
__device__ __forceinline__ void stg32_ef(__half* p, U8 v) {
    asm volatile("st.global.L2::evict_first.v8.b32 [%0], {%1,%2,%3,%4,%5,%6,%7,%8};"
                 :: "l"(p), "r"(v.a.x), "r"(v.a.y), "r"(v.a.z), "r"(v.a.w),
                    "r"(v.b.x), "r"(v.b.y), "r"(v.b.z), "r"(v.b.w) : "memory");
}
__device__ __forceinline__ void stg32_el(__half* p, U8 v) {
    asm volatile("st.global.L2::evict_last.v8.b32 [%0], {%1,%2,%3,%4,%5,%6,%7,%8};"
                 :: "l"(p), "r"(v.a.x), "r"(v.a.y), "r"(v.a.z), "r"(v.a.w),
                    "r"(v.b.x), "r"(v.b.y), "r"(v.b.z), "r"(v.b.w) : "memory");
}

__device__ __forceinline__ uint32_t rsum4(uint32_t a, uint32_t b, uint32_t c, uint32_t d) {
    const __half2 z = __float2half2_rn(0.f);
    __half2 r = __hadd2(__hadd2(__hmax2(u2h(a), z), __hmax2(u2h(b), z)),
                        __hadd2(__hmax2(u2h(c), z), __hmax2(u2h(d), z)));
    return h2u(r);
}
__device__ __forceinline__ uint32_t sum4(uint32_t a, uint32_t b, uint32_t c, uint32_t d) {
    __half2 r = __hadd2(__hadd2(u2h(a), u2h(b)), __hadd2(u2h(c), u2h(d)));
    return h2u(r);
}
__device__ __forceinline__ uint4 rsum16(uint4 a, uint4 b, uint4 c, uint4 d) {
    uint4 o;
    o.x = rsum4(a.x, b.x, c.x, d.x);
    o.y = rsum4(a.y, b.y, c.y, d.y);
    o.z = rsum4(a.z, b.z, c.z, d.z);
    o.w = rsum4(a.w, b.w, c.w, d.w);
    return o;
}
__device__ __forceinline__ uint4 sum16(uint4 a, uint4 b, uint4 c, uint4 d) {
    uint4 o;
    o.x = sum4(a.x, b.x, c.x, d.x);
    o.y = sum4(a.y, b.y, c.y, d.y);
    o.z = sum4(a.z, b.z, c.z, d.z);
    o.w = sum4(a.w, b.w, c.w, d.w);
    return o;
}
__device__ __forceinline__ U8 rsum32(U8 a, U8 b, U8 c, U8 d) {
    U8 o;
    o.a = rsum16(a.a, b.a, c.a, d.a);
    o.b = rsum16(a.b, b.b, c.b, d.b);
    return o;
}
__device__ __forceinline__ U8 sum32(U8 a, U8 b, U8 c, U8 d) {
    U8 o;
    o.a = sum16(a.a, b.a, c.a, d.a);
    o.b = sum16(a.b, b.b, c.b, d.b);
    return o;
}

// ---------------- weight prep (one launch for all 3) ----------------
__global__ void prep_all(const float* __restrict__ W1s,
                         const float* __restrict__ W2s,
                         const float* __restrict__ W3s) {
    int idx = blockIdx.x * 256 + threadIdx.x;
    const int T1 = 320 * KP1, T2 = 320 * KP2;
    const float* W;
    __half* B;
    int KP, mode;
    if (idx < T1) { W = W1s; B = g_W1; KP = KP1; mode = 1; }
    else if (idx < T1 + T2) { idx -= T1; W = W2s; B = g_W2; KP = KP2; mode = 2; }
    else {
        idx -= T1 + T2;
        if (idx >= 320 * KP3) return;
        W = W3s; B = g_W3; KP = KP3; mode = 3;
    }
    int n = idx / KP, k = idx % KP;
    int src;
    if (mode == 3) src = (k < 133) ? k : (k >= 136 && k < 436) ? k - 3 : -1;
    else if (mode == 1) src = (k < K1) ? k : -1;
    else src = (k < DH) ? k : -1;
    float v = (n < 300 && src >= 0) ? W[src * 300 + n] : 0.f;
    B[(size_t)n * KP + k] = __float2half_rn(v);
}

// ---------------- gather1: m1h = sum_j relu(inph[map[j]])  (2 chunks/thread) ----
__global__ void gather_relu(const int* __restrict__ map) {
    int idx = blockIdx.x * 256 + threadIdx.x;
    if (idx >= NB * GT) return;
    int r = idx / GT, c = idx % GT;
    int4 m = ((const int4*)map)[r];
    const int co = c * 16;
    const size_t bx = (size_t)m.x * SROW, by = (size_t)m.y * SROW;
    const size_t bz = (size_t)m.z * SROW, bw = (size_t)m.w * SROW;
    U8 a0 = ldg32_el(g_inph + bx + co), b0 = ldg32_el(g_inph + by + co);
    U8 c0 = ldg32_el(g_inph + bz + co), d0 = ldg32_el(g_inph + bw + co);
    if (c < GT - 1) {
        const int c1 = co + GT * 16;
        U8 a1 = ldg32_el(g_inph + bx + c1), b1 = ldg32_el(g_inph + by + c1);
        U8 c1v = ldg32_el(g_inph + bz + c1), d1 = ldg32_el(g_inph + bw + c1);
        stg32_el(g_m1h + (size_t)r * SROW + co, rsum32(a0, b0, c0, d0));
        stg32_el(g_m1h + (size_t)r * SROW + c1, rsum32(a1, b1, c1v, d1));
    } else {
        stg32_el(g_m1h + (size_t)r * SROW + co, rsum32(a0, b0, c0, d0));
    }
}

// ---------------- gather2: m2h = sum_j m1h[map[j]] -> [NB x 320] ----------------
__global__ void gather2(const int* __restrict__ map) {
    int idx = blockIdx.x * 256 + threadIdx.x;
    if (idx >= NB * GT) return;
    int r = idx / GT, c = idx % GT;
    int4 m = ((const int4*)map)[r];
    const int co = c * 16;
    const size_t bx = (size_t)m.x * SROW, by = (size_t)m.y * SROW;
    const size_t bz = (size_t)m.z * SROW, bw = (size_t)m.w * SROW;
    U8 a0 = ldg32_el(g_m1h + bx + co), b0 = ldg32_el(g_m1h + by + co);
    U8 c0 = ldg32_el(g_m1h + bz + co), d0 = ldg32_el(g_m1h + bw + co);
    if (c < GT - 1) {
        const int c1 = co + GT * 16;
        U8 a1 = ldg32_el(g_m1h + bx + c1), b1 = ldg32_el(g_m1h + by + c1);
        U8 c1v = ldg32_el(g_m1h + bz + c1), d1 = ldg32_el(g_m1h + bw + c1);
        stg32_ef(g_m2h + (size_t)r * KP2 + co, sum32(a0, b0, c0, d0));
        stg32_ef(g_m2h + (size_t)r * KP2 + c1, sum32(a1, b1, c1v, d1));
    } else {
        stg32_ef(g_m2h + (size_t)r * KP2 + co, sum32(a0, b0, c0, d0));
    }
}

// ---------------- gather_atom: msgs = sum_j h2h[a2ib[j]] ----------------
__global__ void gather_atom(const int* __restrict__ a2ib) {
    int idx = blockIdx.x * 256 + threadIdx.x;
    if (idx >= NA * GT) return;
    int r = idx / GT, c = idx % GT;
    int4 m = ((const int4*)a2ib)[r];
    const int co = c * 16;
    const size_t bx = (size_t)m.x * SROW, by = (size_t)m.y * SROW;
    const size_t bz = (size_t)m.z * SROW, bw = (size_t)m.w * SROW;
    U8 a0 = ldg32_el(g_h2h + bx + co), b0 = ldg32_el(g_h2h + by + co);
    U8 c0 = ldg32_el(g_h2h + bz + co), d0 = ldg32_el(g_h2h + bw + co);
    if (c < GT - 1) {
        const int c1 = co + GT * 16;
        U8 a1 = ldg32_el(g_h2h + bx + c1), b1 = ldg32_el(g_h2h + by + c1);
        U8 c1v = ldg32_el(g_h2h + bz + c1), d1 = ldg32_el(g_h2h + bw + c1);
        stg32_ef(g_msgsh + (size_t)r * SROW + co, sum32(a0, b0, c0, d0));
        stg32_ef(g_msgsh + (size_t)r * SROW + c1, sum32(a1, b1, c1v, d1));
    } else {
        stg32_ef(g_msgsh + (size_t)r * SROW + co, sum32(a0, b0, c0, d0));
    }
}

// ---------------- FP16 GEMM: BM=128, BN=320, templated BK, 512 thr, 3 stages ----
// (R15 champion machinery, verbatim.) RS = 2*BK+16 bytes.
template <int MODE, int KP, int BK>
__global__ void __launch_bounds__(512)
mm_f16(const float* __restrict__ srcA,
       const float* __restrict__ bias, float* __restrict__ dOut) {
    constexpr int NCH = KP / BK;
    constexpr int RS = 2 * BK + 16;
    constexpr int BOFF = 128 * RS;
    constexpr int STG = BOFF + 320 * RS;
    constexpr int KPARTS = BK / 32;
    constexpr int NKH = BK / 16;
    const __half* __restrict__ Wt = (MODE == 1) ? g_W1 : (MODE == 2) ? g_W2 : g_W3;

    extern __shared__ __align__(16) char smem[];
    const uint32_t sb = s2u(smem);
    const int tid = threadIdx.x, w = tid >> 5, lane = tid & 31;
    const int wr = w & 1, wc = w >> 1;
    const int rowBase = blockIdx.x * 128;

    float acc[4][5][4];
#pragma unroll
    for (int i = 0; i < 4; i++)
#pragma unroll
        for (int j = 0; j < 5; j++)
#pragma unroll
            for (int q = 0; q < 4; q++) acc[i][j][q] = 0.f;

    __half rbuf[8 * KPARTS];
    auto loadA_regs = [&](int c) {
#pragma unroll
        for (int p = 0; p < KPARTS; p++) {
            const int k = c * BK + p * 32 + lane;
#pragma unroll
            for (int i = 0; i < 8; i++) {
                const int grow = rowBase + w * 8 + i;
                __half v = __float2half_rn(0.f);
                if (MODE == 1) {
                    if (k < K1) v = __float2half_rn(srcA[(size_t)grow * K1 + k]);
                } else if (MODE == 3) {
                    if (k < AF) v = __float2half_rn(srcA[(size_t)grow * AF + k]);
                    else if (k >= 136 && k < 436) v = g_msgsh[(size_t)grow * SROW + (k - 136)];
                }
                rbuf[p * 8 + i] = v;
            }
        }
    };
    auto stsA = [&](int st) {
#pragma unroll
        for (int p = 0; p < KPARTS; p++) {
            char* q = smem + st * STG + (w * 8) * RS + (p * 32 + lane) * 2;
#pragma unroll
            for (int i = 0; i < 8; i++) *(__half*)(q + i * RS) = rbuf[p * 8 + i];
        }
    };

    constexpr int ASEG = BK / 8;
    auto cpA = [&](int c, int st) {
#pragma unroll
        for (int i = tid; i < 128 * ASEG; i += 512) {
            const int row = i / ASEG, seg = i % ASEG;
            cpa16(sb + st * STG + row * RS + seg * 16,
                  g_m2h + (size_t)(rowBase + row) * KP2 + c * BK + seg * 8);
        }
    };
    auto loadB = [&](int c, int st) {
#pragma unroll
        for (int i = tid; i < 320 * ASEG; i += 512) {
            const int row = i / ASEG, seg = i % ASEG;
            cpa16(sb + st * STG + BOFF + row * RS + seg * 16,
                  Wt + (size_t)row * KP + c * BK + seg * 8);
        }
    };

    if (MODE != 2) {
        loadA_regs(0); stsA(0); loadB(0, 0); CP_COMMIT();
        loadA_regs(1); stsA(1); loadB(1, 1); CP_COMMIT();
        loadA_regs(2);
    } else {
        cpA(0, 0); loadB(0, 0); CP_COMMIT();
        cpA(1, 1); loadB(1, 1); CP_COMMIT();
    }

    const uint32_t aOff = (uint32_t)(wr * 64 + (lane & 15)) * RS
                        + (uint32_t)(lane >> 4) * 16;
    const int bl = lane & 15;
    const uint32_t bOff = BOFF + (uint32_t)(wc * 40 + (bl & 7)) * RS
                        + (uint32_t)(bl >> 3) * 16;

    for (int c = 0; c < NCH; c++) {
        CP_WAIT1();
        __syncthreads();
        if (c + 2 < NCH) {
            const int st = (c + 2) % 3;
            if (MODE != 2) { stsA(st); }
            else          { cpA(c + 2, st); }
            loadB(c + 2, st);
        }
        CP_COMMIT();
        if (MODE != 2 && c + 3 < NCH) loadA_regs(c + 3);

        const uint32_t stp = sb + (c % 3) * STG;
#pragma unroll
        for (int kh = 0; kh < NKH; kh++) {
            uint32_t af[4][4], bf[5][2];
#pragma unroll
            for (int mt = 0; mt < 4; mt++)
                ldmx4(af[mt], stp + aOff + mt * (16 * RS) + kh * 32);
#pragma unroll
            for (int nt = 0; nt < 5; nt++)
                ldmx2(bf[nt], stp + bOff + nt * (8 * RS) + kh * 32);
#pragma unroll
            for (int mt = 0; mt < 4; mt++)
#pragma unroll
                for (int nt = 0; nt < 5; nt++)
                    mma_f16(acc[mt][nt], af[mt], bf[nt]);
        }
    }

    if (MODE == 3) {
        const int molBase = blockIdx.x * 4 + wr * 2;
#pragma unroll
        for (int mtb = 0; mtb < 4; mtb += 2) {
#pragma unroll
            for (int nt = 0; nt < 5; nt++) {
                const int col2 = wc * 40 + nt * 8 + (lane & 3) * 2;
                float b0 = 0.f, b1 = 0.f;
                if (col2 < DH) { b0 = bias[col2]; b1 = bias[col2 + 1]; }
                float s0 = 0.f, s1 = 0.f;
#pragma unroll
                for (int p = 0; p < 2; p++) {
#pragma unroll
                    for (int h = 0; h < 2; h++) {
                        s0 += fmaxf(acc[mtb + p][nt][h * 2]     + b0, 0.f);
                        s1 += fmaxf(acc[mtb + p][nt][h * 2 + 1] + b1, 0.f);
                    }
                }
#pragma unroll
                for (int off = 16; off >= 4; off >>= 1) {
                    s0 += __shfl_down_sync(0xFFFFFFFFu, s0, off);
                    s1 += __shfl_down_sync(0xFFFFFFFFu, s1, off);
                }
                if (lane < 4) {
                    const int colw = wc * 40 + nt * 8 + lane * 2;
                    if (colw < DH) {
                        const int mol = molBase + (mtb >> 1);
                        float2 v;
                        v.x = s0 * 0.03125f;
                        v.y = s1 * 0.03125f;
                        *(float2*)&dOut[(size_t)mol * OUTC + colw] = v;
                    }
                }
            }
        }
    } else {
        __half* __restrict__ OUTp = (MODE == 1) ? g_inph : g_h2h;
        const int crow = lane >> 2, cc0 = (lane & 3) * 2;
#pragma unroll
        for (int mt = 0; mt < 4; mt++) {
#pragma unroll
            for (int nt = 0; nt < 5; nt++) {
                const int col = wc * 40 + nt * 8 + cc0;
                if (col >= DH) continue;
#pragma unroll
                for (int half = 0; half < 2; half++) {
                    const int grow = rowBase + wr * 64 + mt * 16 + crow + half * 8;
                    const size_t o = (size_t)grow * SROW + col;
                    float v0 = acc[mt][nt][half * 2];
                    float v1 = acc[mt][nt][half * 2 + 1];
                    if (MODE == 2) {
                        float2 pv = __half22float2(*(const __half2*)&g_inph[o]);
                        v0 = fmaxf(pv.x + v0, 0.f);
                        v1 = fmaxf(pv.y + v1, 0.f);
                    }
                    *(__half2*)&OUTp[o] = __floats2half2_rn(v0, v1);
                }
            }
        }
    }
}

// ---------------- global-feature concat ----------------
__global__ void glob_copy(const float* __restrict__ g, float* __restrict__ out) {
    int idx = blockIdx.x * 256 + threadIdx.x;
    if (idx >= NM * 32) return;
    int mol = idx >> 5, j4 = idx & 31;
    float4 v = ((const float4*)g)[mol * 32 + j4];
    *(float4*)&out[(size_t)mol * OUTC + 300 + 4 * j4] = v;
}

// ---------------- launch ----------------
extern "C" void kernel_launch(void* const* d_in, const int* in_sizes, int n_in,
                              void* d_out, int out_size) {
    const float* atom_features   = (const float*)d_in[0];
    const float* f_ini           = (const float*)d_in[1];
    const float* global_features = (const float*)d_in[2];
    const float* W_i             = (const float*)d_in[3];
    const float* W_h             = (const float*)d_in[4];
    const float* W_o             = (const float*)d_in[5];
    const float* b_o             = (const float*)d_in[6];
    const int*   a2ib            = (const int*)d_in[7];
    const int*   mapping         = (const int*)d_in[8];
    float* out = (float*)d_out;

    const int SM32 = 3 * (448 * 80);    // 107520 (BK=32)
    const int SM64 = 3 * (448 * 144);   // 193536 (BK=64)
    static bool cfg = false;
    if (!cfg) {
        cudaFuncSetAttribute(mm_f16<1, KP1, 32>, cudaFuncAttributeMaxDynamicSharedMemorySize, SM32);
        cudaFuncSetAttribute(mm_f16<2, KP2, 64>, cudaFuncAttributeMaxDynamicSharedMemorySize, SM64);
        cudaFuncSetAttribute(mm_f16<3, KP3, 64>, cudaFuncAttributeMaxDynamicSharedMemorySize, SM64);
        cfg = true;
    }

    glob_copy<<<(NM * 32 + 255) / 256, 256>>>(global_features, out);
    prep_all<<<(320 * (KP1 + KP2 + KP3) + 255) / 256, 256>>>(W_i, W_h, W_o);

    // 1) inp = f_ini @ W_i  (BK=32, 3-stage)
    mm_f16<1, KP1, 32><<<NB / 128, 512, SM32>>>(f_ini, nullptr, nullptr);
    // 2) m1 = sum relu(inp[mapping])   [2 chunks/thread, MLP=8, evict_last]
    gather_relu<<<(NB * GT + 255) / 256, 256>>>(mapping);
    // 3) m2 = sum m1[mapping]
    gather2<<<(NB * GT + 255) / 256, 256>>>(mapping);
    // 4) h2 = relu(inp + m2 @ W_h)  (BK=64, 3-stage)
    mm_f16<2, KP2, 64><<<NB / 128, 512, SM64>>>(nullptr, nullptr, nullptr);
    // 5) msgs = sum h2[a2ib]
    gather_atom<<<(NA * GT + 255) / 256, 256>>>(a2ib);
    // 6+7) out = mean(relu([atomF | msgs] @ W_o + b_o))  (BK=64)
    mm_f16<3, KP3, 64><<<NA / 128, 512, SM64>>>(atom_features, b_o, out);
}